// round 1
// baseline (speedup 1.0000x reference)
#include <cuda_runtime.h>
#include <cuda_bf16.h>
#include <math_constants.h>

// Problem constants (shapes fixed by the dataset; n taken from in_sizes).
#define D 128
#define F 64
#define EPSV 1e-8f
// T = 0.5: logits = sim / T^2 = 4*sim ; pos term = -sim/T = -0.5 * logit
#define INV_T2 4.0f

// ---------------- scratch (no allocations allowed) ----------------
__device__ float  g_sums[F * D];
__device__ int    g_counts[F];
__device__ float  g_pnorm[F];
__device__ uint2  g_bfrag[8 * 8 * 32];   // [ktile][ntile][lane] B-fragments (bf16x2 pairs)
__device__ double g_loss;

// ---------------- helpers ----------------
__device__ __forceinline__ unsigned pack_bf16x2(float lo, float hi) {
    unsigned r;
    asm("cvt.rn.bf16x2.f32 %0, %1, %2;" : "=r"(r) : "f"(hi), "f"(lo));
    return r;
}

__device__ __forceinline__ void mma_bf16(float c[4],
                                         unsigned a0, unsigned a1, unsigned a2, unsigned a3,
                                         unsigned b0, unsigned b1) {
    asm volatile(
        "mma.sync.aligned.m16n8k16.row.col.f32.bf16.bf16.f32 "
        "{%0,%1,%2,%3}, {%4,%5,%6,%7}, {%8,%9}, {%0,%1,%2,%3};"
        : "+f"(c[0]), "+f"(c[1]), "+f"(c[2]), "+f"(c[3])
        : "r"(a0), "r"(a1), "r"(a2), "r"(a3), "r"(b0), "r"(b1));
}

// ---------------- K0: zero scratch (graph determinism) ----------------
__global__ void k_zero() {
    int i = blockIdx.x * blockDim.x + threadIdx.x;
    if (i < F * D) g_sums[i] = 0.0f;
    if (i < F)     g_counts[i] = 0;
    if (i == 0)    g_loss = 0.0;
}

// ---------------- K1: segment sums + counts ----------------
// 128 threads; thread t exclusively owns dim t of the smem accumulator ->
// race-free read-modify-write, no atomics in the hot loop.
__global__ __launch_bounds__(128) void k_segsum(const float* __restrict__ emb,
                                                const int* __restrict__ fams,
                                                int n) {
    __shared__ float acc[F * D];   // 32 KB
    __shared__ int   cnt[F];
    const int t = threadIdx.x;
    #pragma unroll
    for (int i = t; i < F * D; i += 128) acc[i] = 0.0f;
    if (t < F) cnt[t] = 0;
    __syncthreads();

    const int stride = gridDim.x;
    int r = blockIdx.x;
    // unroll-4: hoist loads so the smem RMW chain overlaps memory latency
    for (; r + 3 * stride < n; r += 4 * stride) {
        int   f0 = fams[r];
        int   f1 = fams[r + stride];
        int   f2 = fams[r + 2 * stride];
        int   f3 = fams[r + 3 * stride];
        float v0 = emb[(size_t)r * D + t];
        float v1 = emb[(size_t)(r + stride) * D + t];
        float v2 = emb[(size_t)(r + 2 * stride) * D + t];
        float v3 = emb[(size_t)(r + 3 * stride) * D + t];
        acc[f0 * D + t] += v0;
        acc[f1 * D + t] += v1;
        acc[f2 * D + t] += v2;
        acc[f3 * D + t] += v3;
        if (t == 0) { cnt[f0]++; cnt[f1]++; cnt[f2]++; cnt[f3]++; }
    }
    for (; r < n; r += stride) {
        int f = fams[r];
        acc[f * D + t] += emb[(size_t)r * D + t];
        if (t == 0) cnt[f]++;
    }
    __syncthreads();
    #pragma unroll
    for (int i = t; i < F * D; i += 128) atomicAdd(&g_sums[i], acc[i]);
    if (t < F) atomicAdd(&g_counts[t], cnt[t]);
}

// ---------------- K2: protos (fp32), p_norm (fp32), bf16 B-fragments ----------------
__global__ __launch_bounds__(256) void k_protos() {
    __shared__ float proto[F * D];  // 32 KB fp32 protos
    const int t = threadIdx.x;
    for (int i = t; i < F * D; i += 256) {
        int f = i >> 7;
        float c = (float)g_counts[f];
        proto[i] = g_sums[i] / fmaxf(c, 1.0f);
    }
    __syncthreads();
    // p_norm: 8 warps, families strided by 8
    {
        int lane = t & 31, w = t >> 5;
        for (int f = w; f < F; f += 8) {
            float s = 0.0f;
            #pragma unroll
            for (int j = 0; j < 4; j++) {
                float v = proto[f * D + lane * 4 + j];
                s += v * v;
            }
            #pragma unroll
            for (int o = 16; o > 0; o >>= 1) s += __shfl_xor_sync(0xffffffffu, s, o);
            if (lane == 0) g_pnorm[f] = sqrtf(s);
        }
    }
    // B fragments, exact mma.m16n8k16 B register layout:
    // entry (kt, nt, lane): n = nt*8 + lane/4, k0 = kt*16 + (lane%4)*2
    //   .x = {B[k0][n], B[k0+1][n]}  .y = {B[k0+8][n], B[k0+9][n]}   (lo = smaller k)
    for (int i = t; i < 8 * 8 * 32; i += 256) {
        int lane = i & 31;
        int nt   = (i >> 5) & 7;
        int kt   = i >> 8;
        int nn   = nt * 8 + (lane >> 2);
        int k0   = kt * 16 + (lane & 3) * 2;
        const float* p = proto + nn * D;
        uint2 b;
        b.x = pack_bf16x2(p[k0],     p[k0 + 1]);
        b.y = pack_bf16x2(p[k0 + 8], p[k0 + 9]);
        g_bfrag[i] = b;
    }
}

// ---------------- K3: fused dots (bf16 mma) + cosine + LSE + loss ----------------
__global__ __launch_bounds__(256) void k_loss(const float* __restrict__ emb,
                                              const int* __restrict__ fams,
                                              int n) {
    __shared__ uint2 sB[8 * 8 * 32];   // 16 KB
    __shared__ float sPn[F];
    __shared__ float sRed[8];
    const int t = threadIdx.x;
    for (int i = t; i < 8 * 8 * 32; i += 256) sB[i] = g_bfrag[i];
    if (t < F) sPn[t] = g_pnorm[t];
    __syncthreads();

    const int lane = t & 31, wid = t >> 5;
    const int gw = blockIdx.x * 8 + wid;
    const int nwarps = gridDim.x * 8;
    const int nblocks = n >> 4;   // n is a multiple of 16

    float lsum = 0.0f;

    for (int wb = gw; wb < nblocks; wb += nwarps) {
        const int rbase = wb << 4;
        const int r  = rbase + (lane >> 2);
        const int r2 = r + 8;
        const float* e0 = emb + (size_t)r  * D + (lane & 3) * 2;
        const float* e1 = emb + (size_t)r2 * D + (lane & 3) * 2;

        float acc[8][4];
        #pragma unroll
        for (int nt = 0; nt < 8; nt++)
            #pragma unroll
            for (int j = 0; j < 4; j++) acc[nt][j] = 0.0f;

        float ss0 = 0.0f, ss1 = 0.0f;

        #pragma unroll
        for (int kt = 0; kt < 8; kt++) {
            float2 v00 = *(const float2*)(e0 + kt * 16);
            float2 v10 = *(const float2*)(e1 + kt * 16);
            float2 v01 = *(const float2*)(e0 + kt * 16 + 8);
            float2 v11 = *(const float2*)(e1 + kt * 16 + 8);
            ss0 += v00.x * v00.x + v00.y * v00.y + v01.x * v01.x + v01.y * v01.y;
            ss1 += v10.x * v10.x + v10.y * v10.y + v11.x * v11.x + v11.y * v11.y;
            unsigned a0 = pack_bf16x2(v00.x, v00.y);
            unsigned a1 = pack_bf16x2(v10.x, v10.y);
            unsigned a2 = pack_bf16x2(v01.x, v01.y);
            unsigned a3 = pack_bf16x2(v11.x, v11.y);
            #pragma unroll
            for (int nt = 0; nt < 8; nt++) {
                uint2 b = sB[(kt * 8 + nt) * 32 + lane];
                mma_bf16(acc[nt], a0, a1, a2, a3, b.x, b.y);
            }
        }

        // row norms: reduce sum-of-squares over the 4 lanes of each group
        ss0 += __shfl_xor_sync(0xffffffffu, ss0, 1);
        ss0 += __shfl_xor_sync(0xffffffffu, ss0, 2);
        ss1 += __shfl_xor_sync(0xffffffffu, ss1, 1);
        ss1 += __shfl_xor_sync(0xffffffffu, ss1, 2);
        const float en0 = sqrtf(ss0);
        const float en1 = sqrtf(ss1);

        const int f0 = fams[r];
        const int f1 = fams[r2];

        float max0 = -CUDART_INF_F, max1 = -CUDART_INF_F;
        float pos0 = 0.0f, pos1 = 0.0f;

        #pragma unroll
        for (int nt = 0; nt < 8; nt++) {
            #pragma unroll
            for (int j = 0; j < 2; j++) {
                const int col = nt * 8 + (lane & 3) * 2 + j;
                const float pn = sPn[col];
                const float s0 = INV_T2 / fmaxf(en0 * pn, EPSV);
                const float s1 = INV_T2 / fmaxf(en1 * pn, EPSV);
                float l0 = acc[nt][j]     * s0;
                float l1 = acc[nt][2 + j] * s1;
                acc[nt][j]     = l0;
                acc[nt][2 + j] = l1;
                max0 = fmaxf(max0, l0);
                max1 = fmaxf(max1, l1);
                if (col == f0) pos0 = l0;
                if (col == f1) pos1 = l1;
            }
        }
        // group-of-4 reductions
        max0 = fmaxf(max0, __shfl_xor_sync(0xffffffffu, max0, 1));
        max0 = fmaxf(max0, __shfl_xor_sync(0xffffffffu, max0, 2));
        max1 = fmaxf(max1, __shfl_xor_sync(0xffffffffu, max1, 1));
        max1 = fmaxf(max1, __shfl_xor_sync(0xffffffffu, max1, 2));
        pos0 += __shfl_xor_sync(0xffffffffu, pos0, 1);
        pos0 += __shfl_xor_sync(0xffffffffu, pos0, 2);
        pos1 += __shfl_xor_sync(0xffffffffu, pos1, 1);
        pos1 += __shfl_xor_sync(0xffffffffu, pos1, 2);

        float sum0 = 0.0f, sum1 = 0.0f;
        #pragma unroll
        for (int nt = 0; nt < 8; nt++) {
            sum0 += __expf(acc[nt][0] - max0) + __expf(acc[nt][1] - max0);
            sum1 += __expf(acc[nt][2] - max1) + __expf(acc[nt][3] - max1);
        }
        sum0 += __shfl_xor_sync(0xffffffffu, sum0, 1);
        sum0 += __shfl_xor_sync(0xffffffffu, sum0, 2);
        sum1 += __shfl_xor_sync(0xffffffffu, sum1, 1);
        sum1 += __shfl_xor_sync(0xffffffffu, sum1, 2);

        if ((lane & 3) == 0) {
            // per_sample = -0.5*pos_logit + max + log(sum_exp)
            lsum += (-0.5f * pos0 + max0 + __logf(sum0))
                  + (-0.5f * pos1 + max1 + __logf(sum1));
        }
    }

    // warp + CTA reduction, one double atomic per CTA
    #pragma unroll
    for (int o = 16; o > 0; o >>= 1) lsum += __shfl_xor_sync(0xffffffffu, lsum, o);
    if (lane == 0) sRed[wid] = lsum;
    __syncthreads();
    if (t == 0) {
        float s = 0.0f;
        #pragma unroll
        for (int w = 0; w < 8; w++) s += sRed[w];
        atomicAdd(&g_loss, (double)s);
    }
}

// ---------------- K4: finalize ----------------
__global__ void k_fin(float* __restrict__ out, int n) {
    out[0] = (float)(g_loss / (double)n);
}

// ---------------- launch ----------------
extern "C" void kernel_launch(void* const* d_in, const int* in_sizes, int n_in,
                              void* d_out, int out_size) {
    const float* emb  = (const float*)d_in[0];
    const int*   fams = (const int*)d_in[1];
    const int n = in_sizes[1];           // number of rows
    float* out = (float*)d_out;

    k_zero<<<(F * D + 255) / 256, 256>>>();
    k_segsum<<<592, 128>>>(emb, fams, n);
    k_protos<<<1, 256>>>();
    k_loss<<<296, 256>>>(emb, fams, n);
    k_fin<<<1, 1>>>(out, n);
}

// round 2
// speedup vs baseline: 1.3250x; 1.3250x over previous
#include <cuda_runtime.h>
#include <cuda_bf16.h>
#include <math_constants.h>

#define D 128
#define F 64
#define EPSV 1e-8f
#define INV_T2 4.0f

// ---------------- scratch (no allocations allowed) ----------------
__device__ float  g_sums[F * D];
__device__ int    g_counts[F];
__device__ float  g_pnorm[F];
__device__ uint2  g_bfrag[8 * 8 * 32];   // [ktile][ntile][lane] B-fragments
__device__ double g_loss;

// ---------------- helpers ----------------
__device__ __forceinline__ unsigned pack_bf16x2(float lo, float hi) {
    unsigned r;
    asm("cvt.rn.bf16x2.f32 %0, %1, %2;" : "=r"(r) : "f"(hi), "f"(lo));
    return r;
}

__device__ __forceinline__ void mma_bf16(float c[4],
                                         unsigned a0, unsigned a1, unsigned a2, unsigned a3,
                                         unsigned b0, unsigned b1) {
    asm volatile(
        "mma.sync.aligned.m16n8k16.row.col.f32.bf16.bf16.f32 "
        "{%0,%1,%2,%3}, {%4,%5,%6,%7}, {%8,%9}, {%0,%1,%2,%3};"
        : "+f"(c[0]), "+f"(c[1]), "+f"(c[2]), "+f"(c[3])
        : "r"(a0), "r"(a1), "r"(a2), "r"(a3), "r"(b0), "r"(b1));
}

// ---------------- K0: zero scratch ----------------
__global__ void k_zero() {
    int i = blockIdx.x * blockDim.x + threadIdx.x;
    if (i < F * D) g_sums[i] = 0.0f;
    if (i < F)     g_counts[i] = 0;
    if (i == 0)    g_loss = 0.0;
}

// ---------------- K1: segment sums + counts ----------------
// 128 threads/CTA; thread t exclusively owns dim t -> race-free smem RMW.
// 8-row groups with explicit register prefetch of the next group (MLP=8/warp).
// Counts: cheap smem-atomic histogram over fams only (separate light pass).
#define G 8
__global__ __launch_bounds__(128) void k_segsum(const float* __restrict__ emb,
                                                const int* __restrict__ fams,
                                                int n) {
    __shared__ float acc[F * D];   // 32 KB -> 7 CTAs/SM
    __shared__ int   cnt[F];
    const int t = threadIdx.x;
    #pragma unroll
    for (int i = t; i < F * D; i += 128) acc[i] = 0.0f;
    if (t < F) cnt[t] = 0;
    __syncthreads();

    // counts: histogram over fams (1 MB read, full 128-thread parallelism)
    for (int i = blockIdx.x * 128 + t; i < n; i += gridDim.x * 128)
        atomicAdd(&cnt[fams[i]], 1);

    const int stride = gridDim.x;
    int r = blockIdx.x;

    int   cf[G]; float cv[G];
    int   nf[G]; float nv[G];

    if (r + (G - 1) * stride < n) {
        #pragma unroll
        for (int j = 0; j < G; j++) {
            cf[j] = fams[r + j * stride];
            cv[j] = emb[(size_t)(r + j * stride) * D + t];
        }
        int rn = r + G * stride;
        while (rn + (G - 1) * stride < n) {
            // prefetch next group first (keeps G loads in flight during RMW chain)
            #pragma unroll
            for (int j = 0; j < G; j++) {
                nf[j] = fams[rn + j * stride];
                nv[j] = emb[(size_t)(rn + j * stride) * D + t];
            }
            #pragma unroll
            for (int j = 0; j < G; j++) acc[cf[j] * D + t] += cv[j];
            #pragma unroll
            for (int j = 0; j < G; j++) { cf[j] = nf[j]; cv[j] = nv[j]; }
            rn += G * stride;
        }
        #pragma unroll
        for (int j = 0; j < G; j++) acc[cf[j] * D + t] += cv[j];
        r = rn;
    }
    for (; r < n; r += stride)
        acc[fams[r] * D + t] += emb[(size_t)r * D + t];

    __syncthreads();
    #pragma unroll
    for (int i = t; i < F * D; i += 128) atomicAdd(&g_sums[i], acc[i]);
    if (t < F) atomicAdd(&g_counts[t], cnt[t]);
}

// ---------------- K2: protos (fp32), p_norm, bf16 B-fragments ----------------
__global__ __launch_bounds__(256) void k_protos() {
    __shared__ float proto[F * D];
    const int t = threadIdx.x;
    for (int i = t; i < F * D; i += 256) {
        int f = i >> 7;
        float c = (float)g_counts[f];
        proto[i] = g_sums[i] / fmaxf(c, 1.0f);
    }
    __syncthreads();
    {
        int lane = t & 31, w = t >> 5;
        for (int f = w; f < F; f += 8) {
            float s = 0.0f;
            #pragma unroll
            for (int j = 0; j < 4; j++) {
                float v = proto[f * D + lane * 4 + j];
                s += v * v;
            }
            #pragma unroll
            for (int o = 16; o > 0; o >>= 1) s += __shfl_xor_sync(0xffffffffu, s, o);
            if (lane == 0) g_pnorm[f] = sqrtf(s);
        }
    }
    // B fragments in exact mma.m16n8k16 B register layout
    for (int i = t; i < 8 * 8 * 32; i += 256) {
        int lane = i & 31;
        int nt   = (i >> 5) & 7;
        int kt   = i >> 8;
        int nn   = nt * 8 + (lane >> 2);
        int k0   = kt * 16 + (lane & 3) * 2;
        const float* p = proto + nn * D;
        uint2 b;
        b.x = pack_bf16x2(p[k0],     p[k0 + 1]);
        b.y = pack_bf16x2(p[k0 + 8], p[k0 + 9]);
        g_bfrag[i] = b;
    }
}

// ---------------- K3: fused dots (bf16 mma) + cosine + LSE + loss ----------------
__global__ __launch_bounds__(256, 3) void k_loss(const float* __restrict__ emb,
                                                 const int* __restrict__ fams,
                                                 int n) {
    __shared__ uint2 sB[8 * 8 * 32];   // 16 KB
    __shared__ float sPn[F];
    __shared__ float sRed[8];
    const int t = threadIdx.x;
    for (int i = t; i < 8 * 8 * 32; i += 256) sB[i] = g_bfrag[i];
    if (t < F) sPn[t] = g_pnorm[t];
    __syncthreads();

    const int lane = t & 31, wid = t >> 5;
    const int gw = blockIdx.x * 8 + wid;
    const int nwarps = gridDim.x * 8;
    const int nblocks = n >> 4;

    float lsum = 0.0f;

    for (int wb = gw; wb < nblocks; wb += nwarps) {
        const int rbase = wb << 4;
        const int r  = rbase + (lane >> 2);
        const int r2 = r + 8;
        const float* e0 = emb + (size_t)r  * D + (lane & 3) * 2;
        const float* e1 = emb + (size_t)r2 * D + (lane & 3) * 2;

        // hoist fams off the critical tail
        const int f0 = fams[r];
        const int f1 = fams[r2];

        float acc[8][4];
        #pragma unroll
        for (int nt = 0; nt < 8; nt++)
            #pragma unroll
            for (int j = 0; j < 4; j++) acc[nt][j] = 0.0f;

        float ss0 = 0.0f, ss1 = 0.0f;

        // software pipeline: prefetch kt+1 while mma'ing kt
        float2 v00 = *(const float2*)(e0);
        float2 v10 = *(const float2*)(e1);
        float2 v01 = *(const float2*)(e0 + 8);
        float2 v11 = *(const float2*)(e1 + 8);

        #pragma unroll
        for (int kt = 0; kt < 8; kt++) {
            float2 c00 = v00, c10 = v10, c01 = v01, c11 = v11;
            if (kt < 7) {
                v00 = *(const float2*)(e0 + (kt + 1) * 16);
                v10 = *(const float2*)(e1 + (kt + 1) * 16);
                v01 = *(const float2*)(e0 + (kt + 1) * 16 + 8);
                v11 = *(const float2*)(e1 + (kt + 1) * 16 + 8);
            }
            ss0 += c00.x * c00.x + c00.y * c00.y + c01.x * c01.x + c01.y * c01.y;
            ss1 += c10.x * c10.x + c10.y * c10.y + c11.x * c11.x + c11.y * c11.y;
            unsigned a0 = pack_bf16x2(c00.x, c00.y);
            unsigned a1 = pack_bf16x2(c10.x, c10.y);
            unsigned a2 = pack_bf16x2(c01.x, c01.y);
            unsigned a3 = pack_bf16x2(c11.x, c11.y);
            #pragma unroll
            for (int nt = 0; nt < 8; nt++) {
                uint2 b = sB[(kt * 8 + nt) * 32 + lane];
                mma_bf16(acc[nt], a0, a1, a2, a3, b.x, b.y);
            }
        }

        ss0 += __shfl_xor_sync(0xffffffffu, ss0, 1);
        ss0 += __shfl_xor_sync(0xffffffffu, ss0, 2);
        ss1 += __shfl_xor_sync(0xffffffffu, ss1, 1);
        ss1 += __shfl_xor_sync(0xffffffffu, ss1, 2);
        const float en0 = sqrtf(ss0);
        const float en1 = sqrtf(ss1);

        float max0 = -CUDART_INF_F, max1 = -CUDART_INF_F;
        float pos0 = 0.0f, pos1 = 0.0f;

        #pragma unroll
        for (int nt = 0; nt < 8; nt++) {
            #pragma unroll
            for (int j = 0; j < 2; j++) {
                const int col = nt * 8 + (lane & 3) * 2 + j;
                const float pn = sPn[col];
                const float s0 = INV_T2 / fmaxf(en0 * pn, EPSV);
                const float s1 = INV_T2 / fmaxf(en1 * pn, EPSV);
                float l0 = acc[nt][j]     * s0;
                float l1 = acc[nt][2 + j] * s1;
                acc[nt][j]     = l0;
                acc[nt][2 + j] = l1;
                max0 = fmaxf(max0, l0);
                max1 = fmaxf(max1, l1);
                if (col == f0) pos0 = l0;
                if (col == f1) pos1 = l1;
            }
        }
        max0 = fmaxf(max0, __shfl_xor_sync(0xffffffffu, max0, 1));
        max0 = fmaxf(max0, __shfl_xor_sync(0xffffffffu, max0, 2));
        max1 = fmaxf(max1, __shfl_xor_sync(0xffffffffu, max1, 1));
        max1 = fmaxf(max1, __shfl_xor_sync(0xffffffffu, max1, 2));
        pos0 += __shfl_xor_sync(0xffffffffu, pos0, 1);
        pos0 += __shfl_xor_sync(0xffffffffu, pos0, 2);
        pos1 += __shfl_xor_sync(0xffffffffu, pos1, 1);
        pos1 += __shfl_xor_sync(0xffffffffu, pos1, 2);

        float sum0 = 0.0f, sum1 = 0.0f;
        #pragma unroll
        for (int nt = 0; nt < 8; nt++) {
            sum0 += __expf(acc[nt][0] - max0) + __expf(acc[nt][1] - max0);
            sum1 += __expf(acc[nt][2] - max1) + __expf(acc[nt][3] - max1);
        }
        sum0 += __shfl_xor_sync(0xffffffffu, sum0, 1);
        sum0 += __shfl_xor_sync(0xffffffffu, sum0, 2);
        sum1 += __shfl_xor_sync(0xffffffffu, sum1, 1);
        sum1 += __shfl_xor_sync(0xffffffffu, sum1, 2);

        if ((lane & 3) == 0) {
            lsum += (-0.5f * pos0 + max0 + __logf(sum0))
                  + (-0.5f * pos1 + max1 + __logf(sum1));
        }
    }

    #pragma unroll
    for (int o = 16; o > 0; o >>= 1) lsum += __shfl_xor_sync(0xffffffffu, lsum, o);
    if (lane == 0) sRed[wid] = lsum;
    __syncthreads();
    if (t == 0) {
        float s = 0.0f;
        #pragma unroll
        for (int w = 0; w < 8; w++) s += sRed[w];
        atomicAdd(&g_loss, (double)s);
    }
}

// ---------------- K4: finalize ----------------
__global__ void k_fin(float* __restrict__ out, int n) {
    out[0] = (float)(g_loss / (double)n);
}

// ---------------- launch ----------------
extern "C" void kernel_launch(void* const* d_in, const int* in_sizes, int n_in,
                              void* d_out, int out_size) {
    const float* emb  = (const float*)d_in[0];
    const int*   fams = (const int*)d_in[1];
    const int n = in_sizes[1];
    float* out = (float*)d_out;

    k_zero<<<(F * D + 255) / 256, 256>>>();
    k_segsum<<<1036, 128>>>(emb, fams, n);
    k_protos<<<1, 256>>>();
    k_loss<<<444, 256>>>(emb, fams, n);
    k_fin<<<1, 1>>>(out, n);
}

// round 3
// speedup vs baseline: 1.3434x; 1.0139x over previous
#include <cuda_runtime.h>
#include <cuda_bf16.h>
#include <math_constants.h>

#define D 128
#define F 64
#define INV_T2 4.0f
#define NSEG 1036

// ---------------- scratch (no allocations allowed) ----------------
__device__ float  g_stage[NSEG * F * D];   // per-CTA segsum slabs (~34 MB)
__device__ float  g_sums[F * D];
__device__ int    g_counts[F];
__device__ float  g_pinv[F];               // 4 / p_norm
__device__ uint2  g_bfrag[8 * 8 * 32];
__device__ double g_loss;

// ---------------- helpers ----------------
__device__ __forceinline__ unsigned pack_bf16x2(float lo, float hi) {
    unsigned r;
    asm("cvt.rn.bf16x2.f32 %0, %1, %2;" : "=r"(r) : "f"(hi), "f"(lo));
    return r;
}

__device__ __forceinline__ void mma_bf16(float c[4],
                                         unsigned a0, unsigned a1, unsigned a2, unsigned a3,
                                         unsigned b0, unsigned b1) {
    asm volatile(
        "mma.sync.aligned.m16n8k16.row.col.f32.bf16.bf16.f32 "
        "{%0,%1,%2,%3}, {%4,%5,%6,%7}, {%8,%9}, {%0,%1,%2,%3};"
        : "+f"(c[0]), "+f"(c[1]), "+f"(c[2]), "+f"(c[3])
        : "r"(a0), "r"(a1), "r"(a2), "r"(a3), "r"(b0), "r"(b1));
}

// ---------------- K0: zero ----------------
__global__ void k_zero() {
    int i = blockIdx.x * blockDim.x + threadIdx.x;
    if (i < F * D) g_sums[i] = 0.0f;
    if (i < F)     g_counts[i] = 0;
    if (i == 0)    g_loss = 0.0;
}

// ---------------- K1: segment sums -> private slab (no big atomic flush) ----------------
#define G 8
__global__ __launch_bounds__(128) void k_segsum(const float* __restrict__ emb,
                                                const int* __restrict__ fams,
                                                int n) {
    __shared__ float acc[F * D];   // 32 KB
    __shared__ int   cnt[F];
    const int t = threadIdx.x;
    #pragma unroll
    for (int i = t; i < F * D; i += 128) acc[i] = 0.0f;
    if (t < F) cnt[t] = 0;
    __syncthreads();

    for (int i = blockIdx.x * 128 + t; i < n; i += gridDim.x * 128)
        atomicAdd(&cnt[fams[i]], 1);

    const int stride = gridDim.x;
    int r = blockIdx.x;

    int   cf[G]; float cv[G];
    int   nf[G]; float nv[G];

    if (r + (G - 1) * stride < n) {
        #pragma unroll
        for (int j = 0; j < G; j++) {
            cf[j] = fams[r + j * stride];
            cv[j] = emb[(size_t)(r + j * stride) * D + t];
        }
        int rn = r + G * stride;
        while (rn + (G - 1) * stride < n) {
            #pragma unroll
            for (int j = 0; j < G; j++) {
                nf[j] = fams[rn + j * stride];
                nv[j] = emb[(size_t)(rn + j * stride) * D + t];
            }
            #pragma unroll
            for (int j = 0; j < G; j++) acc[cf[j] * D + t] += cv[j];
            #pragma unroll
            for (int j = 0; j < G; j++) { cf[j] = nf[j]; cv[j] = nv[j]; }
            rn += G * stride;
        }
        #pragma unroll
        for (int j = 0; j < G; j++) acc[cf[j] * D + t] += cv[j];
        r = rn;
    }
    for (; r < n; r += stride)
        acc[fams[r] * D + t] += emb[(size_t)r * D + t];

    __syncthreads();
    // plain coalesced stores to this CTA's slab
    float* st = g_stage + (size_t)blockIdx.x * (F * D);
    #pragma unroll
    for (int i = t; i < F * D; i += 128) st[i] = acc[i];
    if (t < F) atomicAdd(&g_counts[t], cnt[t]);
}

// ---------------- K1b: reduce slabs -> g_sums ----------------
// grid = 64 dim-groups x 8 c-groups = 512 CTAs, 128 threads
__global__ __launch_bounds__(128) void k_reduce() {
    const int t  = threadIdx.x;
    const int dg = blockIdx.x & 63;
    const int cg = blockIdx.x >> 6;
    const int base = dg * 128 + t;
    int c0 = cg * 130;
    int c1 = c0 + 130; if (c1 > NSEG) c1 = NSEG;
    float s = 0.0f;
    int c = c0;
    for (; c + 7 < c1; c += 8) {
        float v0 = g_stage[(size_t)(c + 0) * (F * D) + base];
        float v1 = g_stage[(size_t)(c + 1) * (F * D) + base];
        float v2 = g_stage[(size_t)(c + 2) * (F * D) + base];
        float v3 = g_stage[(size_t)(c + 3) * (F * D) + base];
        float v4 = g_stage[(size_t)(c + 4) * (F * D) + base];
        float v5 = g_stage[(size_t)(c + 5) * (F * D) + base];
        float v6 = g_stage[(size_t)(c + 6) * (F * D) + base];
        float v7 = g_stage[(size_t)(c + 7) * (F * D) + base];
        s += ((v0 + v1) + (v2 + v3)) + ((v4 + v5) + (v6 + v7));
    }
    for (; c < c1; c++) s += g_stage[(size_t)c * (F * D) + base];
    atomicAdd(&g_sums[base], s);
}

// ---------------- K2: protos, 4/p_norm, bf16 B-fragments ----------------
__global__ __launch_bounds__(256) void k_protos() {
    __shared__ float proto[F * D];
    const int t = threadIdx.x;
    for (int i = t; i < F * D; i += 256) {
        int f = i >> 7;
        float c = (float)g_counts[f];
        proto[i] = g_sums[i] / fmaxf(c, 1.0f);
    }
    __syncthreads();
    {
        int lane = t & 31, w = t >> 5;
        for (int f = w; f < F; f += 8) {
            float s = 0.0f;
            #pragma unroll
            for (int j = 0; j < 4; j++) {
                float v = proto[f * D + lane * 4 + j];
                s += v * v;
            }
            #pragma unroll
            for (int o = 16; o > 0; o >>= 1) s += __shfl_xor_sync(0xffffffffu, s, o);
            if (lane == 0) g_pinv[f] = INV_T2 / fmaxf(sqrtf(s), 1e-9f);
        }
    }
    for (int i = t; i < 8 * 8 * 32; i += 256) {
        int lane = i & 31;
        int nt   = (i >> 5) & 7;
        int kt   = i >> 8;
        int nn   = nt * 8 + (lane >> 2);
        int k0   = kt * 16 + (lane & 3) * 2;
        const float* p = proto + nn * D;
        uint2 b;
        b.x = pack_bf16x2(p[k0],     p[k0 + 1]);
        b.y = pack_bf16x2(p[k0 + 8], p[k0 + 9]);
        g_bfrag[i] = b;
    }
}

// ---------------- K3: fused dots + cosine + LSE + loss ----------------
__global__ __launch_bounds__(256, 3) void k_loss(const float* __restrict__ emb,
                                                 const int* __restrict__ fams,
                                                 int n) {
    __shared__ uint2 sB[8 * 8 * 32];
    __shared__ float sPi[F];
    __shared__ float sRed[8];
    const int t = threadIdx.x;
    for (int i = t; i < 8 * 8 * 32; i += 256) sB[i] = g_bfrag[i];
    if (t < F) sPi[t] = g_pinv[t];
    __syncthreads();

    const int lane = t & 31, wid = t >> 5;
    const int nwarps = gridDim.x * 8;
    const int nblocks = n >> 4;
    const int roff  = (lane >> 2);
    const int koff  = (lane & 3) * 2;

    float lsum = 0.0f;

    int wb = blockIdx.x * 8 + wid;
    const float* e0;
    const float* e1;
    int f0 = 0, f1 = 0;
    float2 v00, v10, v01, v11;

    if (wb < nblocks) {
        int r = (wb << 4) + roff;
        e0 = emb + (size_t)r * D + koff;
        e1 = e0 + (size_t)8 * D;
        f0 = fams[r]; f1 = fams[r + 8];
        v00 = *(const float2*)(e0);
        v10 = *(const float2*)(e1);
        v01 = *(const float2*)(e0 + 8);
        v11 = *(const float2*)(e1 + 8);
    }

    while (wb < nblocks) {
        const int wbn = wb + nwarps;
        const bool has_next = wbn < nblocks;
        const float* ne0 = e0;
        const float* ne1 = e1;
        int nf0 = f0, nf1 = f1;

        float acc[8][4];
        #pragma unroll
        for (int nt = 0; nt < 8; nt++)
            #pragma unroll
            for (int j = 0; j < 4; j++) acc[nt][j] = 0.0f;

        float ss0 = 0.0f, ss1 = 0.0f;
        float2 p00, p10, p01, p11;   // next-iteration prefetch regs

        #pragma unroll
        for (int kt = 0; kt < 8; kt++) {
            float2 c00 = v00, c10 = v10, c01 = v01, c11 = v11;
            if (kt < 7) {
                v00 = *(const float2*)(e0 + (kt + 1) * 16);
                v10 = *(const float2*)(e1 + (kt + 1) * 16);
                v01 = *(const float2*)(e0 + (kt + 1) * 16 + 8);
                v11 = *(const float2*)(e1 + (kt + 1) * 16 + 8);
            } else if (has_next) {
                // overlap next block's first loads with the epilogue
                int rn = (wbn << 4) + roff;
                ne0 = emb + (size_t)rn * D + koff;
                ne1 = ne0 + (size_t)8 * D;
                nf0 = fams[rn]; nf1 = fams[rn + 8];
                p00 = *(const float2*)(ne0);
                p10 = *(const float2*)(ne1);
                p01 = *(const float2*)(ne0 + 8);
                p11 = *(const float2*)(ne1 + 8);
            }
            ss0 += c00.x * c00.x + c00.y * c00.y + c01.x * c01.x + c01.y * c01.y;
            ss1 += c10.x * c10.x + c10.y * c10.y + c11.x * c11.x + c11.y * c11.y;
            unsigned a0 = pack_bf16x2(c00.x, c00.y);
            unsigned a1 = pack_bf16x2(c10.x, c10.y);
            unsigned a2 = pack_bf16x2(c01.x, c01.y);
            unsigned a3 = pack_bf16x2(c11.x, c11.y);
            #pragma unroll
            for (int nt = 0; nt < 8; nt++) {
                uint2 b = sB[(kt * 8 + nt) * 32 + lane];
                mma_bf16(acc[nt], a0, a1, a2, a3, b.x, b.y);
            }
        }

        ss0 += __shfl_xor_sync(0xffffffffu, ss0, 1);
        ss0 += __shfl_xor_sync(0xffffffffu, ss0, 2);
        ss1 += __shfl_xor_sync(0xffffffffu, ss1, 1);
        ss1 += __shfl_xor_sync(0xffffffffu, ss1, 2);
        // logit = dot * (4 / (en*pn)); rsqrt replaces sqrt+div
        const float ie0 = rsqrtf(ss0);
        const float ie1 = rsqrtf(ss1);

        float max0 = -CUDART_INF_F, max1 = -CUDART_INF_F;
        float pos0 = 0.0f, pos1 = 0.0f;

        #pragma unroll
        for (int nt = 0; nt < 8; nt++) {
            #pragma unroll
            for (int j = 0; j < 2; j++) {
                const int col = nt * 8 + koff + j;
                const float w = sPi[col];      // broadcast-friendly LDS
                float l0 = acc[nt][j]     * w * ie0;
                float l1 = acc[nt][2 + j] * w * ie1;
                acc[nt][j]     = l0;
                acc[nt][2 + j] = l1;
                max0 = fmaxf(max0, l0);
                max1 = fmaxf(max1, l1);
                if (col == f0) pos0 = l0;
                if (col == f1) pos1 = l1;
            }
        }
        max0 = fmaxf(max0, __shfl_xor_sync(0xffffffffu, max0, 1));
        max0 = fmaxf(max0, __shfl_xor_sync(0xffffffffu, max0, 2));
        max1 = fmaxf(max1, __shfl_xor_sync(0xffffffffu, max1, 1));
        max1 = fmaxf(max1, __shfl_xor_sync(0xffffffffu, max1, 2));
        pos0 += __shfl_xor_sync(0xffffffffu, pos0, 1);
        pos0 += __shfl_xor_sync(0xffffffffu, pos0, 2);
        pos1 += __shfl_xor_sync(0xffffffffu, pos1, 1);
        pos1 += __shfl_xor_sync(0xffffffffu, pos1, 2);

        float sum0 = 0.0f, sum1 = 0.0f;
        #pragma unroll
        for (int nt = 0; nt < 8; nt++) {
            sum0 += __expf(acc[nt][0] - max0) + __expf(acc[nt][1] - max0);
            sum1 += __expf(acc[nt][2] - max1) + __expf(acc[nt][3] - max1);
        }
        sum0 += __shfl_xor_sync(0xffffffffu, sum0, 1);
        sum0 += __shfl_xor_sync(0xffffffffu, sum0, 2);
        sum1 += __shfl_xor_sync(0xffffffffu, sum1, 1);
        sum1 += __shfl_xor_sync(0xffffffffu, sum1, 2);

        if ((lane & 3) == 0) {
            lsum += (-0.5f * pos0 + max0 + __logf(sum0))
                  + (-0.5f * pos1 + max1 + __logf(sum1));
        }

        // rotate prefetched state in
        wb = wbn;
        e0 = ne0; e1 = ne1; f0 = nf0; f1 = nf1;
        v00 = p00; v10 = p10; v01 = p01; v11 = p11;
    }

    #pragma unroll
    for (int o = 16; o > 0; o >>= 1) lsum += __shfl_xor_sync(0xffffffffu, lsum, o);
    if (lane == 0) sRed[wid] = lsum;
    __syncthreads();
    if (t == 0) {
        float s = 0.0f;
        #pragma unroll
        for (int w = 0; w < 8; w++) s += sRed[w];
        atomicAdd(&g_loss, (double)s);
    }
}

// ---------------- K4: finalize ----------------
__global__ void k_fin(float* __restrict__ out, int n) {
    out[0] = (float)(g_loss / (double)n);
}

// ---------------- launch ----------------
extern "C" void kernel_launch(void* const* d_in, const int* in_sizes, int n_in,
                              void* d_out, int out_size) {
    const float* emb  = (const float*)d_in[0];
    const int*   fams = (const int*)d_in[1];
    const int n = in_sizes[1];
    float* out = (float*)d_out;

    k_zero<<<(F * D + 255) / 256, 256>>>();
    k_segsum<<<NSEG, 128>>>(emb, fams, n);
    k_reduce<<<512, 128>>>();
    k_protos<<<1, 256>>>();
    k_loss<<<444, 256>>>(emb, fams, n);
    k_fin<<<1, 1>>>(out, n);
}

// round 4
// speedup vs baseline: 1.4406x; 1.0723x over previous
#include <cuda_runtime.h>
#include <cuda_bf16.h>
#include <math_constants.h>

#define D 128
#define F 64
#define INV_T2 4.0f
#define NSEG 1064   // 7 CTAs/SM x 152 SMs

// ---------------- scratch (no allocations allowed) ----------------
__device__ float  g_stage[NSEG * F * D];   // per-CTA segsum slabs (~35 MB)
__device__ float  g_sums[F * D];
__device__ int    g_counts[F];
__device__ float  g_pinv[F];               // 4 / p_norm
__device__ uint2  g_bfrag[8 * 8 * 32];     // [kt][nt][lane]
__device__ double g_loss;

// ---------------- helpers ----------------
__device__ __forceinline__ unsigned pack_bf16x2(float lo, float hi) {
    unsigned r;
    asm("cvt.rn.bf16x2.f32 %0, %1, %2;" : "=r"(r) : "f"(hi), "f"(lo));
    return r;
}

__device__ __forceinline__ void mma_bf16(float c[4],
                                         unsigned a0, unsigned a1, unsigned a2, unsigned a3,
                                         unsigned b0, unsigned b1) {
    asm volatile(
        "mma.sync.aligned.m16n8k16.row.col.f32.bf16.bf16.f32 "
        "{%0,%1,%2,%3}, {%4,%5,%6,%7}, {%8,%9}, {%0,%1,%2,%3};"
        : "+f"(c[0]), "+f"(c[1]), "+f"(c[2]), "+f"(c[3])
        : "r"(a0), "r"(a1), "r"(a2), "r"(a3), "r"(b0), "r"(b1));
}

// ---------------- K0: zero ----------------
__global__ void k_zero() {
    int i = blockIdx.x * blockDim.x + threadIdx.x;
    if (i < F * D) g_sums[i] = 0.0f;
    if (i < F)     g_counts[i] = 0;
    if (i == 0)    g_loss = 0.0;
}

// ---------------- K1: segment sums -> private slab ----------------
#define G 8
__global__ __launch_bounds__(128) void k_segsum(const float* __restrict__ emb,
                                                const int* __restrict__ fams,
                                                int n) {
    __shared__ float acc[F * D];   // 32 KB
    __shared__ int   cnt[F];
    const int t = threadIdx.x;
    #pragma unroll
    for (int i = t; i < F * D; i += 128) acc[i] = 0.0f;
    if (t < F) cnt[t] = 0;
    __syncthreads();

    for (int i = blockIdx.x * 128 + t; i < n; i += gridDim.x * 128)
        atomicAdd(&cnt[fams[i]], 1);

    const int stride = gridDim.x;
    int r = blockIdx.x;

    int   cf[G]; float cv[G];
    int   nf[G]; float nv[G];

    if (r + (G - 1) * stride < n) {
        #pragma unroll
        for (int j = 0; j < G; j++) {
            cf[j] = fams[r + j * stride];
            cv[j] = emb[(size_t)(r + j * stride) * D + t];
        }
        int rn = r + G * stride;
        while (rn + (G - 1) * stride < n) {
            #pragma unroll
            for (int j = 0; j < G; j++) {
                nf[j] = fams[rn + j * stride];
                nv[j] = emb[(size_t)(rn + j * stride) * D + t];
            }
            #pragma unroll
            for (int j = 0; j < G; j++) acc[cf[j] * D + t] += cv[j];
            #pragma unroll
            for (int j = 0; j < G; j++) { cf[j] = nf[j]; cv[j] = nv[j]; }
            rn += G * stride;
        }
        #pragma unroll
        for (int j = 0; j < G; j++) acc[cf[j] * D + t] += cv[j];
        r = rn;
    }
    for (; r < n; r += stride)
        acc[fams[r] * D + t] += emb[(size_t)r * D + t];

    __syncthreads();
    float* st = g_stage + (size_t)blockIdx.x * (F * D);
    #pragma unroll
    for (int i = t; i < F * D; i += 128) st[i] = acc[i];
    if (t < F) atomicAdd(&g_counts[t], cnt[t]);
}

// ---------------- K1b: reduce slabs -> g_sums ----------------
// grid = 64 dim-groups x 8 c-groups = 512 CTAs, 128 threads
__global__ __launch_bounds__(128) void k_reduce() {
    const int t  = threadIdx.x;
    const int dg = blockIdx.x & 63;
    const int cg = blockIdx.x >> 6;
    const int base = dg * 128 + t;
    int c0 = cg * (NSEG / 8);
    int c1 = c0 + (NSEG / 8);
    float s = 0.0f;
    int c = c0;
    for (; c + 7 < c1; c += 8) {
        float v0 = g_stage[(size_t)(c + 0) * (F * D) + base];
        float v1 = g_stage[(size_t)(c + 1) * (F * D) + base];
        float v2 = g_stage[(size_t)(c + 2) * (F * D) + base];
        float v3 = g_stage[(size_t)(c + 3) * (F * D) + base];
        float v4 = g_stage[(size_t)(c + 4) * (F * D) + base];
        float v5 = g_stage[(size_t)(c + 5) * (F * D) + base];
        float v6 = g_stage[(size_t)(c + 6) * (F * D) + base];
        float v7 = g_stage[(size_t)(c + 7) * (F * D) + base];
        s += ((v0 + v1) + (v2 + v3)) + ((v4 + v5) + (v6 + v7));
    }
    for (; c < c1; c++) s += g_stage[(size_t)c * (F * D) + base];
    atomicAdd(&g_sums[base], s);
}

// ---------------- K2: protos, 4/p_norm, bf16 B-fragments ----------------
// grid = 8 CTAs (one per nt tile = 8 families), 256 threads
__global__ __launch_bounds__(256) void k_protos() {
    __shared__ float proto[8 * D];   // this CTA's 8 families
    const int t  = threadIdx.x;
    const int nt = blockIdx.x;
    const int fbase = nt * 8;

    // protos: 1024 elements / 256 threads = 4 each
    #pragma unroll
    for (int i = t; i < 8 * D; i += 256) {
        int f = fbase + (i >> 7);
        float c = (float)g_counts[f];
        proto[i] = g_sums[f * D + (i & 127)] / fmaxf(c, 1.0f);
    }
    __syncthreads();

    // p_norm: one warp per family
    {
        int lane = t & 31, w = t >> 5;
        float s = 0.0f;
        #pragma unroll
        for (int j = 0; j < 4; j++) {
            float v = proto[w * D + lane * 4 + j];
            s += v * v;
        }
        #pragma unroll
        for (int o = 16; o > 0; o >>= 1) s += __shfl_xor_sync(0xffffffffu, s, o);
        if (lane == 0) g_pinv[fbase + w] = INV_T2 / fmaxf(sqrtf(s), 1e-9f);
    }

    // B fragments for this nt across all kt: 8*32 = 256 entries, 1/thread
    {
        int lane = t & 31;
        int kt   = t >> 5;
        int nl   = lane >> 2;                 // local family 0..7
        int k0   = kt * 16 + (lane & 3) * 2;
        const float* p = proto + nl * D;
        uint2 b;
        b.x = pack_bf16x2(p[k0],     p[k0 + 1]);
        b.y = pack_bf16x2(p[k0 + 8], p[k0 + 9]);
        g_bfrag[(kt * 8 + nt) * 32 + lane] = b;
    }
}

// ---------------- K3: fused dots + cosine + LSE + loss ----------------
__global__ __launch_bounds__(256, 3) void k_loss(const float* __restrict__ emb,
                                                 const int* __restrict__ fams,
                                                 int n) {
    __shared__ uint2 sB[8 * 8 * 32];
    __shared__ float sPi[F];
    __shared__ float sRed[8];
    const int t = threadIdx.x;
    for (int i = t; i < 8 * 8 * 32; i += 256) sB[i] = g_bfrag[i];
    if (t < F) sPi[t] = g_pinv[t];
    __syncthreads();

    const int lane = t & 31, wid = t >> 5;
    const int nwarps = gridDim.x * 8;
    const int nblocks = n >> 4;
    const int roff  = (lane >> 2);
    const int koff  = (lane & 3) * 2;

    float lsum = 0.0f;

    int wb = blockIdx.x * 8 + wid;
    const float* e0;
    const float* e1;
    int f0 = 0, f1 = 0;
    float2 v00, v10, v01, v11;

    if (wb < nblocks) {
        int r = (wb << 4) + roff;
        e0 = emb + (size_t)r * D + koff;
        e1 = e0 + (size_t)8 * D;
        f0 = fams[r]; f1 = fams[r + 8];
        v00 = *(const float2*)(e0);
        v10 = *(const float2*)(e1);
        v01 = *(const float2*)(e0 + 8);
        v11 = *(const float2*)(e1 + 8);
    }

    while (wb < nblocks) {
        const int wbn = wb + nwarps;
        const bool has_next = wbn < nblocks;
        const float* ne0 = e0;
        const float* ne1 = e1;
        int nf0 = f0, nf1 = f1;

        float acc[8][4];
        #pragma unroll
        for (int nt = 0; nt < 8; nt++)
            #pragma unroll
            for (int j = 0; j < 4; j++) acc[nt][j] = 0.0f;

        float ss0 = 0.0f, ss1 = 0.0f;
        float2 p00, p10, p01, p11;

        #pragma unroll
        for (int kt = 0; kt < 8; kt++) {
            float2 c00 = v00, c10 = v10, c01 = v01, c11 = v11;
            if (kt < 7) {
                v00 = *(const float2*)(e0 + (kt + 1) * 16);
                v10 = *(const float2*)(e1 + (kt + 1) * 16);
                v01 = *(const float2*)(e0 + (kt + 1) * 16 + 8);
                v11 = *(const float2*)(e1 + (kt + 1) * 16 + 8);
            } else if (has_next) {
                int rn = (wbn << 4) + roff;
                ne0 = emb + (size_t)rn * D + koff;
                ne1 = ne0 + (size_t)8 * D;
                nf0 = fams[rn]; nf1 = fams[rn + 8];
                p00 = *(const float2*)(ne0);
                p10 = *(const float2*)(ne1);
                p01 = *(const float2*)(ne0 + 8);
                p11 = *(const float2*)(ne1 + 8);
            }
            ss0 += c00.x * c00.x + c00.y * c00.y + c01.x * c01.x + c01.y * c01.y;
            ss1 += c10.x * c10.x + c10.y * c10.y + c11.x * c11.x + c11.y * c11.y;
            unsigned a0 = pack_bf16x2(c00.x, c00.y);
            unsigned a1 = pack_bf16x2(c10.x, c10.y);
            unsigned a2 = pack_bf16x2(c01.x, c01.y);
            unsigned a3 = pack_bf16x2(c11.x, c11.y);
            #pragma unroll
            for (int nt = 0; nt < 8; nt++) {
                uint2 b = sB[(kt * 8 + nt) * 32 + lane];
                mma_bf16(acc[nt], a0, a1, a2, a3, b.x, b.y);
            }
        }

        ss0 += __shfl_xor_sync(0xffffffffu, ss0, 1);
        ss0 += __shfl_xor_sync(0xffffffffu, ss0, 2);
        ss1 += __shfl_xor_sync(0xffffffffu, ss1, 1);
        ss1 += __shfl_xor_sync(0xffffffffu, ss1, 2);
        const float ie0 = rsqrtf(ss0);
        const float ie1 = rsqrtf(ss1);

        float max0 = -CUDART_INF_F, max1 = -CUDART_INF_F;
        float pos0 = 0.0f, pos1 = 0.0f;

        #pragma unroll
        for (int nt = 0; nt < 8; nt++) {
            #pragma unroll
            for (int j = 0; j < 2; j++) {
                const int col = nt * 8 + koff + j;
                const float w = sPi[col];
                float l0 = acc[nt][j]     * w * ie0;
                float l1 = acc[nt][2 + j] * w * ie1;
                acc[nt][j]     = l0;
                acc[nt][2 + j] = l1;
                max0 = fmaxf(max0, l0);
                max1 = fmaxf(max1, l1);
                if (col == f0) pos0 = l0;
                if (col == f1) pos1 = l1;
            }
        }
        max0 = fmaxf(max0, __shfl_xor_sync(0xffffffffu, max0, 1));
        max0 = fmaxf(max0, __shfl_xor_sync(0xffffffffu, max0, 2));
        max1 = fmaxf(max1, __shfl_xor_sync(0xffffffffu, max1, 1));
        max1 = fmaxf(max1, __shfl_xor_sync(0xffffffffu, max1, 2));
        pos0 += __shfl_xor_sync(0xffffffffu, pos0, 1);
        pos0 += __shfl_xor_sync(0xffffffffu, pos0, 2);
        pos1 += __shfl_xor_sync(0xffffffffu, pos1, 1);
        pos1 += __shfl_xor_sync(0xffffffffu, pos1, 2);

        float sum0 = 0.0f, sum1 = 0.0f;
        #pragma unroll
        for (int nt = 0; nt < 8; nt++) {
            sum0 += __expf(acc[nt][0] - max0) + __expf(acc[nt][1] - max0);
            sum1 += __expf(acc[nt][2] - max1) + __expf(acc[nt][3] - max1);
        }
        sum0 += __shfl_xor_sync(0xffffffffu, sum0, 1);
        sum0 += __shfl_xor_sync(0xffffffffu, sum0, 2);
        sum1 += __shfl_xor_sync(0xffffffffu, sum1, 1);
        sum1 += __shfl_xor_sync(0xffffffffu, sum1, 2);

        if ((lane & 3) == 0) {
            lsum += (-0.5f * pos0 + max0 + __logf(sum0))
                  + (-0.5f * pos1 + max1 + __logf(sum1));
        }

        wb = wbn;
        e0 = ne0; e1 = ne1; f0 = nf0; f1 = nf1;
        v00 = p00; v10 = p10; v01 = p01; v11 = p11;
    }

    #pragma unroll
    for (int o = 16; o > 0; o >>= 1) lsum += __shfl_xor_sync(0xffffffffu, lsum, o);
    if (lane == 0) sRed[wid] = lsum;
    __syncthreads();
    if (t == 0) {
        float s = 0.0f;
        #pragma unroll
        for (int w = 0; w < 8; w++) s += sRed[w];
        atomicAdd(&g_loss, (double)s);
    }
}

// ---------------- K4: finalize ----------------
__global__ void k_fin(float* __restrict__ out, int n) {
    out[0] = (float)(g_loss / (double)n);
}

// ---------------- launch ----------------
extern "C" void kernel_launch(void* const* d_in, const int* in_sizes, int n_in,
                              void* d_out, int out_size) {
    const float* emb  = (const float*)d_in[0];
    const int*   fams = (const int*)d_in[1];
    const int n = in_sizes[1];
    float* out = (float*)d_out;

    k_zero<<<(F * D + 255) / 256, 256>>>();
    k_segsum<<<NSEG, 128>>>(emb, fams, n);
    k_reduce<<<512, 128>>>();
    k_protos<<<8, 256>>>();
    k_loss<<<456, 256>>>(emb, fams, n);
    k_fin<<<1, 1>>>(out, n);
}

// round 5
// speedup vs baseline: 1.7843x; 1.2386x over previous
#include <cuda_runtime.h>
#include <cuda_bf16.h>
#include <math_constants.h>

#define D 128
#define F 64
#define INV_T2 4.0f
#define NSEG 912            // 6 CTAs/SM x 152 SMs = exactly one wave
#define RED_CTAS 512
#define CHUNK (NSEG / 8)    // 114 slabs per reduce group

// ---------------- scratch (no allocations allowed) ----------------
__device__ float  g_stage[NSEG * F * D];     // per-CTA segsum slabs (~30 MB)
__device__ int    g_cnt_stage[NSEG * F];
__device__ float  g_part[8 * F * D];         // non-atomic reduce partials
__device__ int    g_cnt_part[8 * F];
__device__ float  g_pinv[F];                 // 4 / p_norm
__device__ uint2  g_bfrag[8 * 8 * 32];       // [kt][nt][lane]
__device__ double g_loss;
__device__ int    g_ticket;

// ---------------- helpers ----------------
__device__ __forceinline__ unsigned pack_bf16x2(float lo, float hi) {
    unsigned r;
    asm("cvt.rn.bf16x2.f32 %0, %1, %2;" : "=r"(r) : "f"(hi), "f"(lo));
    return r;
}

__device__ __forceinline__ void mma_bf16(float c[4],
                                         unsigned a0, unsigned a1, unsigned a2, unsigned a3,
                                         unsigned b0, unsigned b1) {
    asm volatile(
        "mma.sync.aligned.m16n8k16.row.col.f32.bf16.bf16.f32 "
        "{%0,%1,%2,%3}, {%4,%5,%6,%7}, {%8,%9}, {%0,%1,%2,%3};"
        : "+f"(c[0]), "+f"(c[1]), "+f"(c[2]), "+f"(c[3])
        : "r"(a0), "r"(a1), "r"(a2), "r"(a3), "r"(b0), "r"(b1));
}

// ---------------- K1: segment sums -> private slab (no atomics, no pre-zero) ----------------
#define G 8
__global__ __launch_bounds__(128) void k_segsum(const float* __restrict__ emb,
                                                const int* __restrict__ fams,
                                                int n) {
    __shared__ float acc[F * D];   // 32 KB
    __shared__ int   cnt[F];
    const int t = threadIdx.x;
    #pragma unroll
    for (int i = t; i < F * D; i += 128) acc[i] = 0.0f;
    if (t < F) cnt[t] = 0;
    __syncthreads();

    // counts histogram (partition independent of the sum partition — both valid)
    for (int i = blockIdx.x * 128 + t; i < n; i += gridDim.x * 128)
        atomicAdd(&cnt[fams[i]], 1);

    const int stride = gridDim.x;
    int r = blockIdx.x;

    int   cf[G]; float cv[G];
    int   nf[G]; float nv[G];

    if (r + (G - 1) * stride < n) {
        #pragma unroll
        for (int j = 0; j < G; j++) {
            cf[j] = fams[r + j * stride];
            cv[j] = emb[(size_t)(r + j * stride) * D + t];
        }
        int rn = r + G * stride;
        while (rn + (G - 1) * stride < n) {
            #pragma unroll
            for (int j = 0; j < G; j++) {
                nf[j] = fams[rn + j * stride];
                nv[j] = emb[(size_t)(rn + j * stride) * D + t];
            }
            #pragma unroll
            for (int j = 0; j < G; j++) acc[cf[j] * D + t] += cv[j];
            #pragma unroll
            for (int j = 0; j < G; j++) { cf[j] = nf[j]; cv[j] = nv[j]; }
            rn += G * stride;
        }
        #pragma unroll
        for (int j = 0; j < G; j++) acc[cf[j] * D + t] += cv[j];
        r = rn;
    }
    for (; r < n; r += stride)
        acc[fams[r] * D + t] += emb[(size_t)r * D + t];

    __syncthreads();
    float* st = g_stage + (size_t)blockIdx.x * (F * D);
    #pragma unroll
    for (int i = t; i < F * D; i += 128) st[i] = acc[i];
    if (t < F) g_cnt_stage[blockIdx.x * F + t] = cnt[t];
}

// ---------------- K1b: reduce slabs -> 8 non-atomic partials ----------------
// grid = 512 sum-CTAs + 8 count-CTAs
__global__ __launch_bounds__(128) void k_reduce() {
    const int bid = blockIdx.x;
    const int t   = threadIdx.x;
    if (bid < RED_CTAS) {
        const int dg = bid & 63;
        const int cg = bid >> 6;
        const int base = dg * 128 + t;
        const int c0 = cg * CHUNK, c1 = c0 + CHUNK;
        float s = 0.0f;
        int c = c0;
        for (; c + 7 < c1; c += 8) {
            float v0 = g_stage[(size_t)(c + 0) * (F * D) + base];
            float v1 = g_stage[(size_t)(c + 1) * (F * D) + base];
            float v2 = g_stage[(size_t)(c + 2) * (F * D) + base];
            float v3 = g_stage[(size_t)(c + 3) * (F * D) + base];
            float v4 = g_stage[(size_t)(c + 4) * (F * D) + base];
            float v5 = g_stage[(size_t)(c + 5) * (F * D) + base];
            float v6 = g_stage[(size_t)(c + 6) * (F * D) + base];
            float v7 = g_stage[(size_t)(c + 7) * (F * D) + base];
            s += ((v0 + v1) + (v2 + v3)) + ((v4 + v5) + (v6 + v7));
        }
        for (; c < c1; c++) s += g_stage[(size_t)c * (F * D) + base];
        g_part[cg * (F * D) + base] = s;
    } else {
        const int cg = bid - RED_CTAS;        // 0..7
        if (t < F) {
            int s = 0;
            const int c0 = cg * CHUNK, c1 = c0 + CHUNK;
            for (int c = c0; c < c1; c++) s += g_cnt_stage[c * F + t];
            g_cnt_part[cg * F + t] = s;
        }
    }
}

// ---------------- K2: protos, 4/p_norm, bf16 B-fragments ----------------
// grid = 8 CTAs (one per nt tile = 8 families), 256 threads
__global__ __launch_bounds__(256) void k_protos() {
    __shared__ float proto[8 * D];
    const int t  = threadIdx.x;
    const int nt = blockIdx.x;
    const int fbase = nt * 8;

    if (nt == 0 && t == 0) { g_loss = 0.0; g_ticket = 0; }

    #pragma unroll
    for (int i = t; i < 8 * D; i += 256) {
        int f = fbase + (i >> 7);
        int idx = f * D + (i & 127);
        float s = 0.0f;
        #pragma unroll
        for (int cg = 0; cg < 8; cg++) s += g_part[cg * (F * D) + idx];
        int c = 0;
        #pragma unroll
        for (int cg = 0; cg < 8; cg++) c += g_cnt_part[cg * F + f];
        proto[i] = s / fmaxf((float)c, 1.0f);
    }
    __syncthreads();

    {
        int lane = t & 31, w = t >> 5;
        float s = 0.0f;
        #pragma unroll
        for (int j = 0; j < 4; j++) {
            float v = proto[w * D + lane * 4 + j];
            s += v * v;
        }
        #pragma unroll
        for (int o = 16; o > 0; o >>= 1) s += __shfl_xor_sync(0xffffffffu, s, o);
        if (lane == 0) g_pinv[fbase + w] = INV_T2 / fmaxf(sqrtf(s), 1e-9f);
    }

    {
        int lane = t & 31;
        int kt   = t >> 5;
        int nl   = lane >> 2;
        int k0   = kt * 16 + (lane & 3) * 2;
        const float* p = proto + nl * D;
        uint2 b;
        b.x = pack_bf16x2(p[k0],     p[k0 + 1]);
        b.y = pack_bf16x2(p[k0 + 8], p[k0 + 9]);
        g_bfrag[(kt * 8 + nt) * 32 + lane] = b;
    }
}

// ---------------- K3: fused dots + cosine + LSE + loss (+finalize) ----------------
__global__ __launch_bounds__(256, 3) void k_loss(const float* __restrict__ emb,
                                                 const int* __restrict__ fams,
                                                 int n, float* __restrict__ out) {
    __shared__ uint2 sB[8 * 8 * 32];
    __shared__ float sPi[F];
    __shared__ float sRed[8];
    const int t = threadIdx.x;
    for (int i = t; i < 8 * 8 * 32; i += 256) sB[i] = g_bfrag[i];
    if (t < F) sPi[t] = g_pinv[t];
    __syncthreads();

    const int lane = t & 31, wid = t >> 5;
    const int nwarps = gridDim.x * 8;
    const int nblocks = n >> 4;
    const int roff  = (lane >> 2);
    const int koff  = (lane & 3) * 2;

    float lsum = 0.0f;

    int wb = blockIdx.x * 8 + wid;
    const float* e0;
    const float* e1;
    int f0 = 0, f1 = 0;
    // depth-2 pipeline buffers: slot = kt & 1 (8 kt per wb -> phase-invariant)
    float2 buf[2][4];

    if (wb < nblocks) {
        int r = (wb << 4) + roff;
        e0 = emb + (size_t)r * D + koff;
        e1 = e0 + (size_t)8 * D;
        f0 = fams[r]; f1 = fams[r + 8];
        #pragma unroll
        for (int q = 0; q < 2; q++) {
            buf[q][0] = *(const float2*)(e0 + q * 16);
            buf[q][1] = *(const float2*)(e1 + q * 16);
            buf[q][2] = *(const float2*)(e0 + q * 16 + 8);
            buf[q][3] = *(const float2*)(e1 + q * 16 + 8);
        }
    }

    while (wb < nblocks) {
        const int wbn = wb + nwarps;
        const bool has_next = wbn < nblocks;
        const float* ne0 = e0;
        const float* ne1 = e1;
        int nf0 = f0, nf1 = f1;

        float acc[8][4];
        #pragma unroll
        for (int nt = 0; nt < 8; nt++)
            #pragma unroll
            for (int j = 0; j < 4; j++) acc[nt][j] = 0.0f;

        float ss0 = 0.0f, ss1 = 0.0f;

        #pragma unroll
        for (int kt = 0; kt < 8; kt++) {
            const int sl = kt & 1;
            float2 c00 = buf[sl][0], c10 = buf[sl][1], c01 = buf[sl][2], c11 = buf[sl][3];
            if (kt < 6) {
                // prefetch kt+2 into the slot just consumed
                buf[sl][0] = *(const float2*)(e0 + (kt + 2) * 16);
                buf[sl][1] = *(const float2*)(e1 + (kt + 2) * 16);
                buf[sl][2] = *(const float2*)(e0 + (kt + 2) * 16 + 8);
                buf[sl][3] = *(const float2*)(e1 + (kt + 2) * 16 + 8);
            } else if (has_next) {
                // kt==6 -> next wb kt0 into buf[0]; kt==7 -> next wb kt1 into buf[1]
                if (kt == 6) {
                    int rn = (wbn << 4) + roff;
                    ne0 = emb + (size_t)rn * D + koff;
                    ne1 = ne0 + (size_t)8 * D;
                    nf0 = fams[rn]; nf1 = fams[rn + 8];
                }
                const int q = kt - 6;
                buf[sl][0] = *(const float2*)(ne0 + q * 16);
                buf[sl][1] = *(const float2*)(ne1 + q * 16);
                buf[sl][2] = *(const float2*)(ne0 + q * 16 + 8);
                buf[sl][3] = *(const float2*)(ne1 + q * 16 + 8);
            }
            ss0 += c00.x * c00.x + c00.y * c00.y + c01.x * c01.x + c01.y * c01.y;
            ss1 += c10.x * c10.x + c10.y * c10.y + c11.x * c11.x + c11.y * c11.y;
            unsigned a0 = pack_bf16x2(c00.x, c00.y);
            unsigned a1 = pack_bf16x2(c10.x, c10.y);
            unsigned a2 = pack_bf16x2(c01.x, c01.y);
            unsigned a3 = pack_bf16x2(c11.x, c11.y);
            #pragma unroll
            for (int nt = 0; nt < 8; nt++) {
                uint2 b = sB[(kt * 8 + nt) * 32 + lane];
                mma_bf16(acc[nt], a0, a1, a2, a3, b.x, b.y);
            }
        }

        ss0 += __shfl_xor_sync(0xffffffffu, ss0, 1);
        ss0 += __shfl_xor_sync(0xffffffffu, ss0, 2);
        ss1 += __shfl_xor_sync(0xffffffffu, ss1, 1);
        ss1 += __shfl_xor_sync(0xffffffffu, ss1, 2);
        const float ie0 = rsqrtf(ss0);
        const float ie1 = rsqrtf(ss1);

        float max0 = -CUDART_INF_F, max1 = -CUDART_INF_F;
        float pos0 = 0.0f, pos1 = 0.0f;

        #pragma unroll
        for (int nt = 0; nt < 8; nt++) {
            #pragma unroll
            for (int j = 0; j < 2; j++) {
                const int col = nt * 8 + koff + j;
                const float w = sPi[col];
                float l0 = acc[nt][j]     * w * ie0;
                float l1 = acc[nt][2 + j] * w * ie1;
                acc[nt][j]     = l0;
                acc[nt][2 + j] = l1;
                max0 = fmaxf(max0, l0);
                max1 = fmaxf(max1, l1);
                if (col == f0) pos0 = l0;
                if (col == f1) pos1 = l1;
            }
        }
        max0 = fmaxf(max0, __shfl_xor_sync(0xffffffffu, max0, 1));
        max0 = fmaxf(max0, __shfl_xor_sync(0xffffffffu, max0, 2));
        max1 = fmaxf(max1, __shfl_xor_sync(0xffffffffu, max1, 1));
        max1 = fmaxf(max1, __shfl_xor_sync(0xffffffffu, max1, 2));
        pos0 += __shfl_xor_sync(0xffffffffu, pos0, 1);
        pos0 += __shfl_xor_sync(0xffffffffu, pos0, 2);
        pos1 += __shfl_xor_sync(0xffffffffu, pos1, 1);
        pos1 += __shfl_xor_sync(0xffffffffu, pos1, 2);

        float sum0 = 0.0f, sum1 = 0.0f;
        #pragma unroll
        for (int nt = 0; nt < 8; nt++) {
            sum0 += __expf(acc[nt][0] - max0) + __expf(acc[nt][1] - max0);
            sum1 += __expf(acc[nt][2] - max1) + __expf(acc[nt][3] - max1);
        }
        sum0 += __shfl_xor_sync(0xffffffffu, sum0, 1);
        sum0 += __shfl_xor_sync(0xffffffffu, sum0, 2);
        sum1 += __shfl_xor_sync(0xffffffffu, sum1, 1);
        sum1 += __shfl_xor_sync(0xffffffffu, sum1, 2);

        if ((lane & 3) == 0) {
            lsum += (-0.5f * pos0 + max0 + __logf(sum0))
                  + (-0.5f * pos1 + max1 + __logf(sum1));
        }

        wb = wbn;
        e0 = ne0; e1 = ne1; f0 = nf0; f1 = nf1;
    }

    #pragma unroll
    for (int o = 16; o > 0; o >>= 1) lsum += __shfl_xor_sync(0xffffffffu, lsum, o);
    if (lane == 0) sRed[wid] = lsum;
    __syncthreads();
    if (t == 0) {
        float s = 0.0f;
        #pragma unroll
        for (int w = 0; w < 8; w++) s += sRed[w];
        atomicAdd(&g_loss, (double)s);
        __threadfence();
        int v = atomicAdd(&g_ticket, 1);
        if (v == (int)gridDim.x - 1) {
            double total = atomicAdd(&g_loss, 0.0);   // L2-coherent read
            out[0] = (float)(total / (double)n);
        }
    }
}

// ---------------- launch ----------------
extern "C" void kernel_launch(void* const* d_in, const int* in_sizes, int n_in,
                              void* d_out, int out_size) {
    const float* emb  = (const float*)d_in[0];
    const int*   fams = (const int*)d_in[1];
    const int n = in_sizes[1];
    float* out = (float*)d_out;

    k_segsum<<<NSEG, 128>>>(emb, fams, n);
    k_reduce<<<RED_CTAS + 8, 128>>>();
    k_protos<<<8, 256>>>();
    k_loss<<<456, 256>>>(emb, fams, n, out);
}

// round 6
// speedup vs baseline: 1.7940x; 1.0055x over previous
#include <cuda_runtime.h>
#include <cuda_bf16.h>
#include <math_constants.h>

#define D 128
#define F 64
#define INV_T2 4.0f
#define NSEG 912            // 6 CTAs/SM x 152 SMs = exactly one wave
#define RED_CTAS 512
#define CHUNK (NSEG / 8)

// ---------------- scratch (no allocations allowed) ----------------
__device__ float  g_stage[NSEG * F * D];
__device__ int    g_cnt_stage[NSEG * F];
__device__ float  g_part[8 * F * D];
__device__ int    g_cnt_part[8 * F];
__device__ float  g_pinv[F];                 // 4 / p_norm
__device__ uint2  g_bfrag[8 * 8 * 32];       // [kt][nt][lane], PERMUTED k layout
__device__ double g_loss;
__device__ int    g_ticket;

// ---------------- helpers ----------------
__device__ __forceinline__ unsigned pack_bf16x2(float lo, float hi) {
    unsigned r;
    asm("cvt.rn.bf16x2.f32 %0, %1, %2;" : "=r"(r) : "f"(hi), "f"(lo));
    return r;
}

__device__ __forceinline__ void mma_bf16(float c[4],
                                         unsigned a0, unsigned a1, unsigned a2, unsigned a3,
                                         unsigned b0, unsigned b1) {
    asm volatile(
        "mma.sync.aligned.m16n8k16.row.col.f32.bf16.bf16.f32 "
        "{%0,%1,%2,%3}, {%4,%5,%6,%7}, {%8,%9}, {%0,%1,%2,%3};"
        : "+f"(c[0]), "+f"(c[1]), "+f"(c[2]), "+f"(c[3])
        : "r"(a0), "r"(a1), "r"(a2), "r"(a3), "r"(b0), "r"(b1));
}

// ---------------- K1: segment sums -> private slab ----------------
#define G 8
__global__ __launch_bounds__(128) void k_segsum(const float* __restrict__ emb,
                                                const int* __restrict__ fams,
                                                int n) {
    __shared__ float acc[F * D];
    __shared__ int   cnt[F];
    const int t = threadIdx.x;
    #pragma unroll
    for (int i = t; i < F * D; i += 128) acc[i] = 0.0f;
    if (t < F) cnt[t] = 0;
    __syncthreads();

    for (int i = blockIdx.x * 128 + t; i < n; i += gridDim.x * 128)
        atomicAdd(&cnt[fams[i]], 1);

    const int stride = gridDim.x;
    int r = blockIdx.x;

    int   cf[G]; float cv[G];
    int   nf[G]; float nv[G];

    if (r + (G - 1) * stride < n) {
        #pragma unroll
        for (int j = 0; j < G; j++) {
            cf[j] = fams[r + j * stride];
            cv[j] = emb[(size_t)(r + j * stride) * D + t];
        }
        int rn = r + G * stride;
        while (rn + (G - 1) * stride < n) {
            #pragma unroll
            for (int j = 0; j < G; j++) {
                nf[j] = fams[rn + j * stride];
                nv[j] = emb[(size_t)(rn + j * stride) * D + t];
            }
            #pragma unroll
            for (int j = 0; j < G; j++) acc[cf[j] * D + t] += cv[j];
            #pragma unroll
            for (int j = 0; j < G; j++) { cf[j] = nf[j]; cv[j] = nv[j]; }
            rn += G * stride;
        }
        #pragma unroll
        for (int j = 0; j < G; j++) acc[cf[j] * D + t] += cv[j];
        r = rn;
    }
    for (; r < n; r += stride)
        acc[fams[r] * D + t] += emb[(size_t)r * D + t];

    __syncthreads();
    float* st = g_stage + (size_t)blockIdx.x * (F * D);
    #pragma unroll
    for (int i = t; i < F * D; i += 128) st[i] = acc[i];
    if (t < F) g_cnt_stage[blockIdx.x * F + t] = cnt[t];
}

// ---------------- K1b: reduce slabs -> 8 non-atomic partials ----------------
__global__ __launch_bounds__(128) void k_reduce() {
    const int bid = blockIdx.x;
    const int t   = threadIdx.x;
    if (bid < RED_CTAS) {
        const int dg = bid & 63;
        const int cg = bid >> 6;
        const int base = dg * 128 + t;
        const int c0 = cg * CHUNK, c1 = c0 + CHUNK;
        float s = 0.0f;
        int c = c0;
        for (; c + 7 < c1; c += 8) {
            float v0 = g_stage[(size_t)(c + 0) * (F * D) + base];
            float v1 = g_stage[(size_t)(c + 1) * (F * D) + base];
            float v2 = g_stage[(size_t)(c + 2) * (F * D) + base];
            float v3 = g_stage[(size_t)(c + 3) * (F * D) + base];
            float v4 = g_stage[(size_t)(c + 4) * (F * D) + base];
            float v5 = g_stage[(size_t)(c + 5) * (F * D) + base];
            float v6 = g_stage[(size_t)(c + 6) * (F * D) + base];
            float v7 = g_stage[(size_t)(c + 7) * (F * D) + base];
            s += ((v0 + v1) + (v2 + v3)) + ((v4 + v5) + (v6 + v7));
        }
        for (; c < c1; c++) s += g_stage[(size_t)c * (F * D) + base];
        g_part[cg * (F * D) + base] = s;
    } else {
        const int cg = bid - RED_CTAS;
        if (t < F) {
            int s = 0;
            const int c0 = cg * CHUNK, c1 = c0 + CHUNK;
            for (int c = c0; c < c1; c++) s += g_cnt_stage[c * F + t];
            g_cnt_part[cg * F + t] = s;
        }
    }
}

// ---------------- K2: protos, 4/p_norm, PERMUTED bf16 B-fragments ----------------
__global__ __launch_bounds__(256) void k_protos() {
    __shared__ float proto[8 * D];
    const int t  = threadIdx.x;
    const int nt = blockIdx.x;
    const int fbase = nt * 8;

    if (nt == 0 && t == 0) { g_loss = 0.0; g_ticket = 0; }

    #pragma unroll
    for (int i = t; i < 8 * D; i += 256) {
        int f = fbase + (i >> 7);
        int idx = f * D + (i & 127);
        float s = 0.0f;
        #pragma unroll
        for (int cg = 0; cg < 8; cg++) s += g_part[cg * (F * D) + idx];
        int c = 0;
        #pragma unroll
        for (int cg = 0; cg < 8; cg++) c += g_cnt_part[cg * F + f];
        proto[i] = s / fmaxf((float)c, 1.0f);
    }
    __syncthreads();

    {
        int lane = t & 31, w = t >> 5;
        float s = 0.0f;
        #pragma unroll
        for (int j = 0; j < 4; j++) {
            float v = proto[w * D + lane * 4 + j];
            s += v * v;
        }
        #pragma unroll
        for (int o = 16; o > 0; o >>= 1) s += __shfl_xor_sync(0xffffffffu, s, o);
        if (lane == 0) g_pinv[fbase + w] = INV_T2 / fmaxf(sqrtf(s), 1e-9f);
    }

    // PERMUTED k layout: lane c covers k = kt*16 + 4c .. 4c+3
    //   b.x = {P[k0], P[k0+1]} pairs with A slot a0; b.y = {P[k0+2], P[k0+3]} pairs with a2
    {
        int lane = t & 31;
        int kt   = t >> 5;
        int nl   = lane >> 2;
        int k0   = kt * 16 + (lane & 3) * 4;
        const float* p = proto + nl * D;
        uint2 b;
        b.x = pack_bf16x2(p[k0],     p[k0 + 1]);
        b.y = pack_bf16x2(p[k0 + 2], p[k0 + 3]);
        g_bfrag[(kt * 8 + nt) * 32 + lane] = b;
    }
}

// ---------------- K3: fused dots + cosine + LSE + loss (+finalize) ----------------
__global__ __launch_bounds__(256, 3) void k_loss(const float* __restrict__ emb,
                                                 const int* __restrict__ fams,
                                                 int n, float* __restrict__ out) {
    __shared__ uint2 sB[8 * 8 * 32];
    __shared__ float sPi[F];
    __shared__ float sRed[8];
    const int t = threadIdx.x;
    for (int i = t; i < 8 * 8 * 32; i += 256) sB[i] = g_bfrag[i];
    if (t < F) sPi[t] = g_pinv[t];
    __syncthreads();

    const int lane = t & 31, wid = t >> 5;
    const int nwarps = gridDim.x * 8;
    const int nblocks = n >> 4;
    const int roff  = (lane >> 2);
    const int koff  = (lane & 3) * 4;     // permuted: 4 consecutive elements per lane

    float lsum = 0.0f;

    int wb = blockIdx.x * 8 + wid;
    const float* e0;
    const float* e1;
    int f0 = 0, f1 = 0;
    float4 buf[2][2];                     // [slot][row0/row1], depth-2

    if (wb < nblocks) {
        int r = (wb << 4) + roff;
        e0 = emb + (size_t)r * D + koff;
        e1 = e0 + (size_t)8 * D;
        f0 = fams[r]; f1 = fams[r + 8];
        #pragma unroll
        for (int q = 0; q < 2; q++) {
            buf[q][0] = *(const float4*)(e0 + q * 16);
            buf[q][1] = *(const float4*)(e1 + q * 16);
        }
    }

    while (wb < nblocks) {
        const int wbn = wb + nwarps;
        const bool has_next = wbn < nblocks;
        const float* ne0 = e0;
        const float* ne1 = e1;
        int nf0 = f0, nf1 = f1;

        float acc[8][4];
        #pragma unroll
        for (int nt = 0; nt < 8; nt++)
            #pragma unroll
            for (int j = 0; j < 4; j++) acc[nt][j] = 0.0f;

        float ss0 = 0.0f, ss1 = 0.0f;

        #pragma unroll
        for (int kt = 0; kt < 8; kt++) {
            const int sl = kt & 1;
            float4 c0 = buf[sl][0], c1 = buf[sl][1];
            if (kt < 6) {
                buf[sl][0] = *(const float4*)(e0 + (kt + 2) * 16);
                buf[sl][1] = *(const float4*)(e1 + (kt + 2) * 16);
            } else if (has_next) {
                if (kt == 6) {
                    int rn = (wbn << 4) + roff;
                    ne0 = emb + (size_t)rn * D + koff;
                    ne1 = ne0 + (size_t)8 * D;
                    nf0 = fams[rn]; nf1 = fams[rn + 8];
                }
                const int q = kt - 6;
                buf[sl][0] = *(const float4*)(ne0 + q * 16);
                buf[sl][1] = *(const float4*)(ne1 + q * 16);
            }
            ss0 += c0.x * c0.x + c0.y * c0.y + c0.z * c0.z + c0.w * c0.w;
            ss1 += c1.x * c1.x + c1.y * c1.y + c1.z * c1.z + c1.w * c1.w;
            unsigned a0 = pack_bf16x2(c0.x, c0.y);
            unsigned a2 = pack_bf16x2(c0.z, c0.w);
            unsigned a1 = pack_bf16x2(c1.x, c1.y);
            unsigned a3 = pack_bf16x2(c1.z, c1.w);
            #pragma unroll
            for (int nt = 0; nt < 8; nt++) {
                uint2 b = sB[(kt * 8 + nt) * 32 + lane];
                mma_bf16(acc[nt], a0, a1, a2, a3, b.x, b.y);
            }
        }

        ss0 += __shfl_xor_sync(0xffffffffu, ss0, 1);
        ss0 += __shfl_xor_sync(0xffffffffu, ss0, 2);
        ss1 += __shfl_xor_sync(0xffffffffu, ss1, 1);
        ss1 += __shfl_xor_sync(0xffffffffu, ss1, 2);
        const float ie0 = rsqrtf(ss0);
        const float ie1 = rsqrtf(ss1);

        // logits bounded in [-4,4] -> no max subtraction needed for LSE
        float pos0 = 0.0f, pos1 = 0.0f;
        float sum0 = 0.0f, sum1 = 0.0f;
        const int cbase = (lane & 3) * 2;

        #pragma unroll
        for (int nt = 0; nt < 8; nt++) {
            #pragma unroll
            for (int j = 0; j < 2; j++) {
                const int col = nt * 8 + cbase + j;
                const float w = sPi[col];
                float l0 = acc[nt][j]     * w * ie0;
                float l1 = acc[nt][2 + j] * w * ie1;
                sum0 += __expf(l0);
                sum1 += __expf(l1);
                if (col == f0) pos0 = l0;
                if (col == f1) pos1 = l1;
            }
        }
        pos0 += __shfl_xor_sync(0xffffffffu, pos0, 1);
        pos0 += __shfl_xor_sync(0xffffffffu, pos0, 2);
        pos1 += __shfl_xor_sync(0xffffffffu, pos1, 1);
        pos1 += __shfl_xor_sync(0xffffffffu, pos1, 2);
        sum0 += __shfl_xor_sync(0xffffffffu, sum0, 1);
        sum0 += __shfl_xor_sync(0xffffffffu, sum0, 2);
        sum1 += __shfl_xor_sync(0xffffffffu, sum1, 1);
        sum1 += __shfl_xor_sync(0xffffffffu, sum1, 2);

        if ((lane & 3) == 0) {
            lsum += (-0.5f * pos0 + __logf(sum0))
                  + (-0.5f * pos1 + __logf(sum1));
        }

        wb = wbn;
        e0 = ne0; e1 = ne1; f0 = nf0; f1 = nf1;
    }

    #pragma unroll
    for (int o = 16; o > 0; o >>= 1) lsum += __shfl_xor_sync(0xffffffffu, lsum, o);
    if (lane == 0) sRed[wid] = lsum;
    __syncthreads();
    if (t == 0) {
        float s = 0.0f;
        #pragma unroll
        for (int w = 0; w < 8; w++) s += sRed[w];
        atomicAdd(&g_loss, (double)s);
        __threadfence();
        int v = atomicAdd(&g_ticket, 1);
        if (v == (int)gridDim.x - 1) {
            double total = atomicAdd(&g_loss, 0.0);
            out[0] = (float)(total / (double)n);
        }
    }
}

// ---------------- launch ----------------
extern "C" void kernel_launch(void* const* d_in, const int* in_sizes, int n_in,
                              void* d_out, int out_size) {
    const float* emb  = (const float*)d_in[0];
    const int*   fams = (const int*)d_in[1];
    const int n = in_sizes[1];
    float* out = (float*)d_out;

    k_segsum<<<NSEG, 128>>>(emb, fams, n);
    k_reduce<<<RED_CTAS + 8, 128>>>();
    k_protos<<<8, 256>>>();
    k_loss<<<456, 256>>>(emb, fams, n, out);
}